// round 8
// baseline (speedup 1.0000x reference)
#include <cuda_runtime.h>
#include <math.h>

#define BB 32
#define TT 50
#define SS 2048
#define CC 8
#define FF 32
#define SH 1024
#define SH_PAD 1040     // SH + 16 zero pad rows (halo reads)
#define NG 128          // 4*F gates
#define RDIM 80         // 16 (x patch) + 64 (h patch)
#define POSB 64         // owned output positions per block
#define TS 8            // max fused timesteps per launch
#define SLOTS 72        // computed slots per block (8 warps * NP)
#define NP 9            // slots per warp
#define NTHREADS 256
#define HROWS 73        // smem h rows (reads reach row 72)
#define CROWS 72        // smem c rows (unconditional reads reach row 71)
#define XTOT (BB*TT*SS*CC)

typedef unsigned long long ull;

// Persistent device state (zeroed every kernel_launch call; pad rows stay 0)
__device__ float g_h[BB][SH_PAD][FF];
__device__ float g_c[BB][SH_PAD][FF];
__device__ float4 g_w4[RDIM][FF];          // [r][f] -> (gate0, gate1, gate2, gate3)

__device__ __forceinline__ float hsig(float x) {
    return __saturatef(fmaf(x, 0.2f, 0.5f));
}

// fast tanh: 1 - 2/(exp(2x)+1); abs err ~1e-6, exact saturation
__device__ __forceinline__ float ftanh(float x) {
    float e = __expf(2.0f * x);
    return 1.0f - __fdividef(2.0f, e + 1.0f);
}

// packed f32x2 helpers
__device__ __forceinline__ ull fma2(ull a, ull b, ull c) {
    ull d;
    asm("fma.rn.f32x2 %0, %1, %2, %3;" : "=l"(d) : "l"(a), "l"(b), "l"(c));
    return d;
}
__device__ __forceinline__ ull dup2(float v) {
    ull d;
    asm("mov.b64 %0, {%1, %1};" : "=l"(d) : "f"(v));
    return d;
}
__device__ __forceinline__ ull pack2(float lo, float hi) {
    ull d;
    asm("mov.b64 %0, {%1, %2};" : "=l"(d) : "f"(lo), "f"(hi));
    return d;
}
__device__ __forceinline__ float2 unpack2(ull d) {
    float lo, hi;
    asm("mov.b64 {%0, %1}, %2;" : "=f"(lo), "=f"(hi) : "l"(d));
    return make_float2(lo, hi);
}

__global__ void zero_state_kernel() {
    size_t idx = (size_t)blockIdx.x * blockDim.x + threadIdx.x;
    size_t stride = (size_t)gridDim.x * blockDim.x;
    float* h = &g_h[0][0][0];
    float* c = &g_c[0][0][0];
    const size_t n = (size_t)BB * SH_PAD * FF;
    for (size_t i = idx; i < n; i += stride) { h[i] = 0.0f; c[i] = 0.0f; }
}

// Repack weights: row r of the 80-wide reduction.
__global__ void prep_w_kernel(const float* __restrict__ kern,
                              const float* __restrict__ rk) {
    int i = blockIdx.x * blockDim.x + threadIdx.x;
    if (i >= RDIM * FF) return;
    int r = i / FF, f = i % FF;
    const float* src;
    if (r < 16) {
        int k = r >> 3, c = r & 7;
        src = kern + (k * CC + c) * NG;
    } else {
        int rr = r - 16;
        int k = rr >> 5, ff = rr & 31;
        src = rk + (k * FF + ff) * NG;
    }
    g_w4[r][f] = make_float4(src[f], src[32 + f], src[64 + f], src[96 + f]);
}

// Fused up-to-TS timesteps. Grid: (SH/POSB, BB) = (16, 32).
// smem floats: w4s 10240 | xs 72*16=1152 | hsD 73*32 ull = 4672 fl | cs 72*32 = 2304
__global__ __launch_bounds__(NTHREADS, 3)
void step_kernel(const float* __restrict__ x, const float* __restrict__ bias,
                 int t0, int ts) {
    extern __shared__ float smem[];
    float4* w4s = (float4*)smem;                     // 2560 float4
    float* xs  = smem + RDIM * FF * 4;               // 1152 floats
    ull*   hsD = (ull*)(xs + SLOTS * 16);            // 73*32 duplicated pairs
    float* cs  = (float*)(hsD + HROWS * FF);         // 2304 floats

    const int b = blockIdx.y;
    const int p0 = blockIdx.x * POSB;
    const int tid = threadIdx.x;

    // ---- one-time fills
    {
        const float4* wsrc = &g_w4[0][0];
        #pragma unroll
        for (int i = tid; i < RDIM * FF; i += NTHREADS) w4s[i] = wsrc[i];
        const float* hsrc = &g_h[b][p0][0];
        #pragma unroll
        for (int i = tid; i < HROWS * FF; i += NTHREADS) hsD[i] = dup2(hsrc[i]);
        const float* csrc = &g_c[b][p0][0];
        #pragma unroll
        for (int i = tid; i < CROWS * FF; i += NTHREADS) cs[i] = csrc[i];
        // xs for step 0
        const size_t base = (((size_t)b * TT + t0) * SS + 2 * p0) * CC;
        #pragma unroll
        for (int i = tid; i < SLOTS * 16; i += NTHREADS) {
            size_t gi = base + i;
            xs[i] = (gi < (size_t)XTOT) ? x[gi] : 0.0f;
        }
    }

    const int f = tid & 31;
    const int w = tid >> 5;
    const int pl = w * NP;   // warp's local slot base

    const ull b01 = pack2(bias[f], bias[32 + f]);
    const ull b23 = pack2(bias[64 + f], bias[96 + f]);

    __syncthreads();

    for (int s = 0; s < ts; s++) {
        const int width = POSB + (ts - 1 - s);

        // acc[j][0] = packed (gate0,gate1), acc[j][1] = packed (gate2,gate3)
        ull acc[NP][2];
        #pragma unroll
        for (int j = 0; j < NP; j++) { acc[j][0] = b01; acc[j][1] = b23; }

        // ---- x-patch (r = 0..15): 4-row weight groups, float4 patches
        #pragma unroll
        for (int rg = 0; rg < 4; rg++) {
            ulonglong2 wv0 = *(const ulonglong2*)&w4s[(rg * 4 + 0) * FF + f];
            ulonglong2 wv1 = *(const ulonglong2*)&w4s[(rg * 4 + 1) * FF + f];
            ulonglong2 wv2 = *(const ulonglong2*)&w4s[(rg * 4 + 2) * FF + f];
            ulonglong2 wv3 = *(const ulonglong2*)&w4s[(rg * 4 + 3) * FF + f];
            #pragma unroll
            for (int j = 0; j < NP; j++) {
                float4 pv = *(const float4*)&xs[(pl + j) * 16 + rg * 4];
                ull d0 = dup2(pv.x), d1 = dup2(pv.y);
                ull d2 = dup2(pv.z), d3 = dup2(pv.w);
                acc[j][0] = fma2(d0, wv0.x, acc[j][0]);
                acc[j][1] = fma2(d0, wv0.y, acc[j][1]);
                acc[j][0] = fma2(d1, wv1.x, acc[j][0]);
                acc[j][1] = fma2(d1, wv1.y, acc[j][1]);
                acc[j][0] = fma2(d2, wv2.x, acc[j][0]);
                acc[j][1] = fma2(d2, wv2.y, acc[j][1]);
                acc[j][0] = fma2(d3, wv3.x, acc[j][0]);
                acc[j][1] = fma2(d3, wv3.y, acc[j][1]);
            }
        }

        // ---- h-patch: row-major merge of k0/k1 taps; duplicated pairs from smem.
        // h row m feeds slot m via k0 weights and slot m-1 via k1 weights.
        #pragma unroll
        for (int fg = 0; fg < FF / 2; fg++) {
            ulonglong2 w0a = *(const ulonglong2*)&w4s[(16 + fg * 2 + 0) * FF + f];
            ulonglong2 w0b = *(const ulonglong2*)&w4s[(16 + fg * 2 + 1) * FF + f];
            ulonglong2 w1a = *(const ulonglong2*)&w4s[(16 + FF + fg * 2 + 0) * FF + f];
            ulonglong2 w1b = *(const ulonglong2*)&w4s[(16 + FF + fg * 2 + 1) * FF + f];
            #pragma unroll
            for (int m = 0; m <= NP; m++) {
                // (h[row, 2fg], h[row, 2fg]) and (h[row, 2fg+1], ...) pre-duplicated
                ulonglong2 hv = *(const ulonglong2*)&hsD[(pl + m) * FF + fg * 2];
                if (m < NP) {
                    acc[m][0] = fma2(hv.x, w0a.x, acc[m][0]);
                    acc[m][1] = fma2(hv.x, w0a.y, acc[m][1]);
                    acc[m][0] = fma2(hv.y, w0b.x, acc[m][0]);
                    acc[m][1] = fma2(hv.y, w0b.y, acc[m][1]);
                }
                if (m > 0) {
                    acc[m - 1][0] = fma2(hv.x, w1a.x, acc[m - 1][0]);
                    acc[m - 1][1] = fma2(hv.x, w1a.y, acc[m - 1][1]);
                    acc[m - 1][0] = fma2(hv.y, w1b.x, acc[m - 1][0]);
                    acc[m - 1][1] = fma2(hv.y, w1b.y, acc[m - 1][1]);
                }
            }
        }

        __syncthreads();   // all reads of hsD / xs complete

        // ---- cell update: in-place h write (masked beyond wedge / spatial edge)
        #pragma unroll
        for (int j = 0; j < NP; j++) {
            const int m = pl + j;
            const int p = p0 + m;
            float cold = cs[m * FF + f];
            float2 a01 = unpack2(acc[j][0]);   // (zi, zf)
            float2 a23 = unpack2(acc[j][1]);   // (zc, zo)
            float i_g = hsig(a01.x);
            float f_g = hsig(a01.y);
            float cn = f_g * cold + i_g * ftanh(a23.x);
            float o_g = hsig(a23.y);
            float hn = o_g * ftanh(cn);
            bool ok = (m < width) && (p < SH);
            hsD[m * FF + f] = dup2(ok ? hn : 0.0f);
            if (ok) cs[m * FF + f] = cn;
        }

        // ---- prefetch xs for next step (xs readers finished at barrier above)
        if (s + 1 < ts) {
            const size_t base = (((size_t)b * TT + (t0 + s + 1)) * SS + 2 * p0) * CC;
            #pragma unroll
            for (int i = tid; i < SLOTS * 16; i += NTHREADS) {
                size_t gi = base + i;
                xs[i] = (gi < (size_t)XTOT) ? x[gi] : 0.0f;
            }
        }
        __syncthreads();   // h/c/xs writes visible
    }

    // ---- writeback owned rows
    #pragma unroll
    for (int j = 0; j < NP; j++) {
        const int m = pl + j;
        if (m < POSB) {
            g_h[b][p0 + m][f] = unpack2(hsD[m * FF + f]).x;
            g_c[b][p0 + m][f] = cs[m * FF + f];
        }
    }
}

// out[b] = sum(h_final[b] * dense_w) + dense_b
__global__ __launch_bounds__(256)
void dense_kernel(const float* __restrict__ dw, const float* __restrict__ db,
                  float* __restrict__ out) {
    const int b = blockIdx.x;
    const float* h = &g_h[b][0][0];   // rows 0..SH-1 contiguous
    float s = 0.0f;
    for (int i = threadIdx.x; i < SH * FF; i += 256) s += h[i] * dw[i];
    #pragma unroll
    for (int off = 16; off > 0; off >>= 1) s += __shfl_down_sync(0xffffffffu, s, off);
    __shared__ float red[8];
    int lane = threadIdx.x & 31, wid = threadIdx.x >> 5;
    if (lane == 0) red[wid] = s;
    __syncthreads();
    if (wid == 0) {
        s = (lane < 8) ? red[lane] : 0.0f;
        #pragma unroll
        for (int off = 4; off > 0; off >>= 1) s += __shfl_down_sync(0xffffffffu, s, off);
        if (lane == 0) out[b] = s + db[0];
    }
}

extern "C" void kernel_launch(void* const* d_in, const int* in_sizes, int n_in,
                              void* d_out, int out_size) {
    const float* x    = (const float*)d_in[0];  // (32,50,2048,8)
    const float* kern = (const float*)d_in[1];  // (2,8,128)
    const float* rk   = (const float*)d_in[2];  // (2,32,128)
    const float* bias = (const float*)d_in[3];  // (128,)
    const float* dw   = (const float*)d_in[4];  // (32768,1)
    const float* db   = (const float*)d_in[5];  // (1,)
    float* out = (float*)d_out;                  // (32,1)

    const int smem_bytes = (RDIM * FF * 4 + SLOTS * 16 + 2 * HROWS * FF + CROWS * FF) * 4;
    static int configured = 0;
    if (!configured) {
        cudaFuncSetAttribute(step_kernel, cudaFuncAttributeMaxDynamicSharedMemorySize,
                             smem_bytes);
        configured = 1;
    }

    zero_state_kernel<<<512, 256>>>();
    prep_w_kernel<<<(RDIM * FF + 255) / 256, 256>>>(kern, rk);

    dim3 grid(SH / POSB, BB);
    for (int t0 = 0; t0 < TT; t0 += TS) {
        int ts = (TT - t0 < TS) ? (TT - t0) : TS;
        step_kernel<<<grid, NTHREADS, smem_bytes>>>(x, bias, t0, ts);
    }
    dense_kernel<<<BB, 256>>>(dw, db, out);
}

// round 9
// speedup vs baseline: 1.0898x; 1.0898x over previous
#include <cuda_runtime.h>
#include <math.h>

#define BB 32
#define TT 50
#define SS 2048
#define CC 8
#define FF 32
#define SH 1024
#define SH_PAD 1040     // SH + 16 zero pad rows (halo reads)
#define NG 128          // 4*F gates
#define RDIM 80         // 16 (x patch) + 64 (h patch)
#define POSB 256        // owned output positions per block
#define TS 8            // max fused timesteps per launch
#define NWARPS 24
#define NP 11           // slots per warp
#define SLOTS (NWARPS*NP)   // 264 computed slots (wedge needs 256+7=263)
#define NTHREADS 768
#define HROWS 265       // smem h rows (reads reach row 264)
#define CROWS 264       // smem c rows (unconditional reads reach row 263)
#define XTOT (BB*TT*SS*CC)

typedef unsigned long long ull;

// Persistent device state (zeroed every kernel_launch call; pad rows stay 0)
__device__ float g_h[BB][SH_PAD][FF];
__device__ float g_c[BB][SH_PAD][FF];
__device__ float4 g_w4[RDIM][FF];          // [r][f] -> (gate0, gate1, gate2, gate3)

__device__ __forceinline__ float hsig(float x) {
    return __saturatef(fmaf(x, 0.2f, 0.5f));
}

// fast tanh: 1 - 2/(exp(2x)+1); abs err ~1e-6, exact saturation
__device__ __forceinline__ float ftanh(float x) {
    float e = __expf(2.0f * x);
    return 1.0f - __fdividef(2.0f, e + 1.0f);
}

// packed f32x2 helpers
__device__ __forceinline__ ull fma2(ull a, ull b, ull c) {
    ull d;
    asm("fma.rn.f32x2 %0, %1, %2, %3;" : "=l"(d) : "l"(a), "l"(b), "l"(c));
    return d;
}
__device__ __forceinline__ ull dup2(float v) {
    ull d;
    asm("mov.b64 %0, {%1, %1};" : "=l"(d) : "f"(v));
    return d;
}
__device__ __forceinline__ ull pack2(float lo, float hi) {
    ull d;
    asm("mov.b64 %0, {%1, %2};" : "=l"(d) : "f"(lo), "f"(hi));
    return d;
}
__device__ __forceinline__ float2 unpack2(ull d) {
    float lo, hi;
    asm("mov.b64 {%0, %1}, %2;" : "=f"(lo), "=f"(hi) : "l"(d));
    return make_float2(lo, hi);
}

__global__ void zero_state_kernel() {
    size_t idx = (size_t)blockIdx.x * blockDim.x + threadIdx.x;
    size_t stride = (size_t)gridDim.x * blockDim.x;
    float* h = &g_h[0][0][0];
    float* c = &g_c[0][0][0];
    const size_t n = (size_t)BB * SH_PAD * FF;
    for (size_t i = idx; i < n; i += stride) { h[i] = 0.0f; c[i] = 0.0f; }
}

// Repack weights: row r of the 80-wide reduction.
__global__ void prep_w_kernel(const float* __restrict__ kern,
                              const float* __restrict__ rk) {
    int i = blockIdx.x * blockDim.x + threadIdx.x;
    if (i >= RDIM * FF) return;
    int r = i / FF, f = i % FF;
    const float* src;
    if (r < 16) {
        int k = r >> 3, c = r & 7;
        src = kern + (k * CC + c) * NG;
    } else {
        int rr = r - 16;
        int k = rr >> 5, ff = rr & 31;
        src = rk + (k * FF + ff) * NG;
    }
    g_w4[r][f] = make_float4(src[f], src[32 + f], src[64 + f], src[96 + f]);
}

// Fused up-to-TS timesteps. Grid: (SH/POSB, BB) = (4, 32) = 128 blocks -> 1/SM, one wave.
// smem: w4s 40960B | xs 16896B | hsD 67840B | cs 33792B  -> 159488B
__global__ __launch_bounds__(NTHREADS, 1)
void step_kernel(const float* __restrict__ x, const float* __restrict__ bias,
                 int t0, int ts) {
    extern __shared__ float smem[];
    float4* w4s = (float4*)smem;                     // 2560 float4
    float* xs  = smem + RDIM * FF * 4;               // SLOTS*16 floats
    ull*   hsD = (ull*)(xs + SLOTS * 16);            // HROWS*32 duplicated pairs
    float* cs  = (float*)(hsD + HROWS * FF);         // CROWS*32 floats

    const int b = blockIdx.y;
    const int p0 = blockIdx.x * POSB;
    const int tid = threadIdx.x;

    // ---- one-time fills
    {
        const float4* wsrc = &g_w4[0][0];
        #pragma unroll
        for (int i = tid; i < RDIM * FF; i += NTHREADS) w4s[i] = wsrc[i];
        const float* hsrc = &g_h[b][p0][0];
        #pragma unroll
        for (int i = tid; i < HROWS * FF; i += NTHREADS) hsD[i] = dup2(hsrc[i]);
        const float* csrc = &g_c[b][p0][0];
        #pragma unroll
        for (int i = tid; i < CROWS * FF; i += NTHREADS) cs[i] = csrc[i];
        // xs for step 0
        const size_t base = (((size_t)b * TT + t0) * SS + 2 * p0) * CC;
        #pragma unroll
        for (int i = tid; i < SLOTS * 16; i += NTHREADS) {
            size_t gi = base + i;
            xs[i] = (gi < (size_t)XTOT) ? x[gi] : 0.0f;
        }
    }

    const int f = tid & 31;
    const int w = tid >> 5;
    const int pl = w * NP;   // warp's local slot base

    const ull b01 = pack2(bias[f], bias[32 + f]);
    const ull b23 = pack2(bias[64 + f], bias[96 + f]);

    __syncthreads();

    for (int s = 0; s < ts; s++) {
        const int width = POSB + (ts - 1 - s);

        // acc[j][0] = packed (gate0,gate1), acc[j][1] = packed (gate2,gate3)
        ull acc[NP][2];
        #pragma unroll
        for (int j = 0; j < NP; j++) { acc[j][0] = b01; acc[j][1] = b23; }

        // ---- x-patch (r = 0..15): 4-row weight groups, float4 patches
        #pragma unroll
        for (int rg = 0; rg < 4; rg++) {
            ulonglong2 wv0 = *(const ulonglong2*)&w4s[(rg * 4 + 0) * FF + f];
            ulonglong2 wv1 = *(const ulonglong2*)&w4s[(rg * 4 + 1) * FF + f];
            ulonglong2 wv2 = *(const ulonglong2*)&w4s[(rg * 4 + 2) * FF + f];
            ulonglong2 wv3 = *(const ulonglong2*)&w4s[(rg * 4 + 3) * FF + f];
            #pragma unroll
            for (int j = 0; j < NP; j++) {
                float4 pv = *(const float4*)&xs[(pl + j) * 16 + rg * 4];
                ull d0 = dup2(pv.x), d1 = dup2(pv.y);
                ull d2 = dup2(pv.z), d3 = dup2(pv.w);
                acc[j][0] = fma2(d0, wv0.x, acc[j][0]);
                acc[j][1] = fma2(d0, wv0.y, acc[j][1]);
                acc[j][0] = fma2(d1, wv1.x, acc[j][0]);
                acc[j][1] = fma2(d1, wv1.y, acc[j][1]);
                acc[j][0] = fma2(d2, wv2.x, acc[j][0]);
                acc[j][1] = fma2(d2, wv2.y, acc[j][1]);
                acc[j][0] = fma2(d3, wv3.x, acc[j][0]);
                acc[j][1] = fma2(d3, wv3.y, acc[j][1]);
            }
        }

        // ---- h-patch: row-major merge of k0/k1 taps; duplicated pairs from smem.
        // h row m feeds slot m via k0 weights and slot m-1 via k1 weights.
        #pragma unroll
        for (int fg = 0; fg < FF / 2; fg++) {
            ulonglong2 w0a = *(const ulonglong2*)&w4s[(16 + fg * 2 + 0) * FF + f];
            ulonglong2 w0b = *(const ulonglong2*)&w4s[(16 + fg * 2 + 1) * FF + f];
            ulonglong2 w1a = *(const ulonglong2*)&w4s[(16 + FF + fg * 2 + 0) * FF + f];
            ulonglong2 w1b = *(const ulonglong2*)&w4s[(16 + FF + fg * 2 + 1) * FF + f];
            #pragma unroll
            for (int m = 0; m <= NP; m++) {
                ulonglong2 hv = *(const ulonglong2*)&hsD[(pl + m) * FF + fg * 2];
                if (m < NP) {
                    acc[m][0] = fma2(hv.x, w0a.x, acc[m][0]);
                    acc[m][1] = fma2(hv.x, w0a.y, acc[m][1]);
                    acc[m][0] = fma2(hv.y, w0b.x, acc[m][0]);
                    acc[m][1] = fma2(hv.y, w0b.y, acc[m][1]);
                }
                if (m > 0) {
                    acc[m - 1][0] = fma2(hv.x, w1a.x, acc[m - 1][0]);
                    acc[m - 1][1] = fma2(hv.x, w1a.y, acc[m - 1][1]);
                    acc[m - 1][0] = fma2(hv.y, w1b.x, acc[m - 1][0]);
                    acc[m - 1][1] = fma2(hv.y, w1b.y, acc[m - 1][1]);
                }
            }
        }

        __syncthreads();   // all reads of hsD / xs complete

        // ---- cell update: in-place h write (masked beyond wedge / spatial edge)
        #pragma unroll
        for (int j = 0; j < NP; j++) {
            const int m = pl + j;
            const int p = p0 + m;
            float cold = cs[m * FF + f];
            float2 a01 = unpack2(acc[j][0]);   // (zi, zf)
            float2 a23 = unpack2(acc[j][1]);   // (zc, zo)
            float i_g = hsig(a01.x);
            float f_g = hsig(a01.y);
            float cn = f_g * cold + i_g * ftanh(a23.x);
            float o_g = hsig(a23.y);
            float hn = o_g * ftanh(cn);
            bool ok = (m < width) && (p < SH);
            hsD[m * FF + f] = dup2(ok ? hn : 0.0f);
            if (ok) cs[m * FF + f] = cn;
        }

        // ---- prefetch xs for next step (xs readers finished at barrier above)
        if (s + 1 < ts) {
            const size_t base = (((size_t)b * TT + (t0 + s + 1)) * SS + 2 * p0) * CC;
            #pragma unroll
            for (int i = tid; i < SLOTS * 16; i += NTHREADS) {
                size_t gi = base + i;
                xs[i] = (gi < (size_t)XTOT) ? x[gi] : 0.0f;
            }
        }
        __syncthreads();   // h/c/xs writes visible
    }

    // ---- writeback owned rows
    #pragma unroll
    for (int j = 0; j < NP; j++) {
        const int m = pl + j;
        if (m < POSB) {
            g_h[b][p0 + m][f] = unpack2(hsD[m * FF + f]).x;
            g_c[b][p0 + m][f] = cs[m * FF + f];
        }
    }
}

// out[b] = sum(h_final[b] * dense_w) + dense_b
__global__ __launch_bounds__(256)
void dense_kernel(const float* __restrict__ dw, const float* __restrict__ db,
                  float* __restrict__ out) {
    const int b = blockIdx.x;
    const float* h = &g_h[b][0][0];   // rows 0..SH-1 contiguous
    float s = 0.0f;
    for (int i = threadIdx.x; i < SH * FF; i += 256) s += h[i] * dw[i];
    #pragma unroll
    for (int off = 16; off > 0; off >>= 1) s += __shfl_down_sync(0xffffffffu, s, off);
    __shared__ float red[8];
    int lane = threadIdx.x & 31, wid = threadIdx.x >> 5;
    if (lane == 0) red[wid] = s;
    __syncthreads();
    if (wid == 0) {
        s = (lane < 8) ? red[lane] : 0.0f;
        #pragma unroll
        for (int off = 4; off > 0; off >>= 1) s += __shfl_down_sync(0xffffffffu, s, off);
        if (lane == 0) out[b] = s + db[0];
    }
}

extern "C" void kernel_launch(void* const* d_in, const int* in_sizes, int n_in,
                              void* d_out, int out_size) {
    const float* x    = (const float*)d_in[0];  // (32,50,2048,8)
    const float* kern = (const float*)d_in[1];  // (2,8,128)
    const float* rk   = (const float*)d_in[2];  // (2,32,128)
    const float* bias = (const float*)d_in[3];  // (128,)
    const float* dw   = (const float*)d_in[4];  // (32768,1)
    const float* db   = (const float*)d_in[5];  // (1,)
    float* out = (float*)d_out;                  // (32,1)

    const int smem_bytes = RDIM * FF * 16 + SLOTS * 16 * 4 + HROWS * FF * 8 + CROWS * FF * 4;
    static int configured = 0;
    if (!configured) {
        cudaFuncSetAttribute(step_kernel, cudaFuncAttributeMaxDynamicSharedMemorySize,
                             smem_bytes);
        configured = 1;
    }

    zero_state_kernel<<<512, 256>>>();
    prep_w_kernel<<<(RDIM * FF + 255) / 256, 256>>>(kern, rk);

    dim3 grid(SH / POSB, BB);
    for (int t0 = 0; t0 < TT; t0 += TS) {
        int ts = (TT - t0 < TS) ? (TT - t0) : TS;
        step_kernel<<<grid, NTHREADS, smem_bytes>>>(x, bias, t0, ts);
    }
    dense_kernel<<<BB, 256>>>(dw, db, out);
}